// round 1
// baseline (speedup 1.0000x reference)
#include <cuda_runtime.h>
#include <math.h>

#define BT_ 32      // B*T
#define H_ 8
#define L_ 512
#define E_ 64       // KD = VD
#define D_ 512

// Scratch for projected Q/K/V, layout (bt, h, l, e)  -> 32 MB each
__device__ float g_Q[BT_ * H_ * L_ * E_];
__device__ float g_K[BT_ * H_ * L_ * E_];
__device__ float g_V[BT_ * H_ * L_ * E_];

// ---------------------------------------------------------------------------
// Projection GEMM: C(16384 x 512) = X(16384 x 512) * W(512 x 512)
// scatter-written to out[(bt*8 + h)*512 + l)*64 + e] with m = bt*512 + l,
// n = h*64 + e. 128x128 block tile, BK=16, 256 threads, 8x8 microtile.
// ---------------------------------------------------------------------------
__global__ __launch_bounds__(256) void proj_kernel(const float* __restrict__ X,
                                                   const float* __restrict__ W,
                                                   float* __restrict__ out) {
    __shared__ float Ast[16][132];   // A transposed: Ast[k][m]
    __shared__ float Bs[16][132];    // Bs[k][n]

    const int tid = threadIdx.x;
    const int tr = tid >> 4;         // 0..15
    const int tc = tid & 15;         // 0..15
    const int bm = blockIdx.x * 128;
    const int bn = blockIdx.y * 128;

    float acc[8][8];
#pragma unroll
    for (int i = 0; i < 8; i++)
#pragma unroll
        for (int j = 0; j < 8; j++) acc[i][j] = 0.f;

    for (int k0 = 0; k0 < 512; k0 += 16) {
        // Load A tile: rows bm..bm+127, cols k0..k0+15 (4 float4 per row)
#pragma unroll
        for (int j = 0; j < 2; j++) {
            int f   = j * 256 + tid;          // 512 float4s
            int row = f >> 2;
            int c4  = (f & 3) * 4;
            float4 v = *(const float4*)(X + (size_t)(bm + row) * 512 + k0 + c4);
            Ast[c4 + 0][row] = v.x;
            Ast[c4 + 1][row] = v.y;
            Ast[c4 + 2][row] = v.z;
            Ast[c4 + 3][row] = v.w;
        }
        // Load B tile: rows k0..k0+15, cols bn..bn+127 (32 float4 per row)
#pragma unroll
        for (int j = 0; j < 2; j++) {
            int f   = j * 256 + tid;
            int row = f >> 5;
            int c4  = (f & 31) * 4;
            float4 v = *(const float4*)(W + (size_t)(k0 + row) * 512 + bn + c4);
            *(float4*)&Bs[row][c4] = v;
        }
        __syncthreads();

#pragma unroll
        for (int k = 0; k < 16; k++) {
            float a[8], b[8];
#pragma unroll
            for (int i = 0; i < 8; i++) a[i] = Ast[k][tr + 16 * i];
#pragma unroll
            for (int i = 0; i < 8; i++) b[i] = Bs[k][tc + 16 * i];
#pragma unroll
            for (int i = 0; i < 8; i++)
#pragma unroll
                for (int j = 0; j < 8; j++) acc[i][j] += a[i] * b[j];
        }
        __syncthreads();
    }

    // Scatter-write to (bt, h, l, e)
#pragma unroll
    for (int i = 0; i < 8; i++) {
        int m  = bm + tr + 16 * i;
        int bt = m >> 9;
        int l  = m & 511;
#pragma unroll
        for (int j = 0; j < 8; j++) {
            int n = bn + tc + 16 * j;
            int h = n >> 6;
            int e = n & 63;
            out[(((size_t)(bt * 8 + h) * 512) + l) * 64 + e] = acc[i][j];
        }
    }
}

// ---------------------------------------------------------------------------
// Flash attention. One block per (bt, 64-row tile). Loops over h internally
// and accumulates w_head[h] * softmax((a*QK^T + c)*mask) @ V into fp32 regs.
// 256 threads, 4x4 microtile per thread with strided mapping (tr+16i, tc+16j).
// Dynamic smem: Qs, Ks, Vs, Ps each 64x65 fp32.
// ---------------------------------------------------------------------------
__global__ __launch_bounds__(256) void attn_kernel(const float* __restrict__ mask,
                                                   const float* __restrict__ w_head,
                                                   const float* __restrict__ tau_p,
                                                   const float* __restrict__ delta_p,
                                                   float* __restrict__ out) {
    extern __shared__ float sm[];
    float* Qs = sm;               // 64*65
    float* Ks = sm + 4160;
    float* Vs = sm + 8320;
    float* Ps = sm + 12480;

    const int tid  = threadIdx.x;
    const int tr   = tid >> 4;
    const int tc   = tid & 15;
    const int bt   = blockIdx.y;
    const int row0 = blockIdx.x * 64;

    const float a_scl = tau_p[0] * 0.125f;     // tau * (1/sqrt(64))
    const float c_add = delta_p[0] * 0.125f;   // delta * (1/sqrt(64))

    float fin[4][4];
#pragma unroll
    for (int i = 0; i < 4; i++)
#pragma unroll
        for (int j = 0; j < 4; j++) fin[i][j] = 0.f;

    for (int h = 0; h < 8; h++) {
        const float* Qg = g_Q + (((size_t)(bt * 8 + h) * 512) + row0) * 64;
        const float* Kg = g_K + ((size_t)(bt * 8 + h) * 512) * 64;
        const float* Vg = g_V + ((size_t)(bt * 8 + h) * 512) * 64;

        __syncthreads();   // protect Qs from previous head's readers
        // Load Q tile (64 x 64)
#pragma unroll
        for (int j = 0; j < 4; j++) {
            int f   = j * 256 + tid;    // 1024 float4s
            int row = f >> 4;
            int c   = (f & 15) * 4;
            float4 v = *(const float4*)(Qg + row * 64 + c);
            Qs[row * 65 + c + 0] = v.x;
            Qs[row * 65 + c + 1] = v.y;
            Qs[row * 65 + c + 2] = v.z;
            Qs[row * 65 + c + 3] = v.w;
        }

        float m_[4], l_[4], oacc[4][4];
#pragma unroll
        for (int i = 0; i < 4; i++) {
            m_[i] = -INFINITY;
            l_[i] = 0.f;
#pragma unroll
            for (int j = 0; j < 4; j++) oacc[i][j] = 0.f;
        }

        for (int jb = 0; jb < 8; jb++) {
            __syncthreads();   // Q loaded / previous P*V complete
            // Load K, V tiles (64 keys x 64 dims)
#pragma unroll
            for (int j = 0; j < 4; j++) {
                int f   = j * 256 + tid;
                int row = f >> 4;
                int c   = (f & 15) * 4;
                float4 vk = *(const float4*)(Kg + (jb * 64 + row) * 64 + c);
                Ks[row * 65 + c + 0] = vk.x;
                Ks[row * 65 + c + 1] = vk.y;
                Ks[row * 65 + c + 2] = vk.z;
                Ks[row * 65 + c + 3] = vk.w;
                float4 vv = *(const float4*)(Vg + (jb * 64 + row) * 64 + c);
                Vs[row * 65 + c + 0] = vv.x;
                Vs[row * 65 + c + 1] = vv.y;
                Vs[row * 65 + c + 2] = vv.z;
                Vs[row * 65 + c + 3] = vv.w;
            }
            __syncthreads();

            // S = Q * K^T  (64x64 tile, 4x4 per thread)
            float s[4][4];
#pragma unroll
            for (int i = 0; i < 4; i++)
#pragma unroll
                for (int j = 0; j < 4; j++) s[i][j] = 0.f;
#pragma unroll 4
            for (int kk = 0; kk < 64; kk++) {
                float q[4], kv[4];
#pragma unroll
                for (int i = 0; i < 4; i++) q[i]  = Qs[(tr + 16 * i) * 65 + kk];
#pragma unroll
                for (int i = 0; i < 4; i++) kv[i] = Ks[(tc + 16 * i) * 65 + kk];
#pragma unroll
                for (int i = 0; i < 4; i++)
#pragma unroll
                    for (int j = 0; j < 4; j++) s[i][j] += q[i] * kv[j];
            }

            // de-stationary rescale + scale + multiplicative mask
#pragma unroll
            for (int i = 0; i < 4; i++) {
                int gr = row0 + tr + 16 * i;
#pragma unroll
                for (int j = 0; j < 4; j++) {
                    int gc = jb * 64 + tc + 16 * j;
                    s[i][j] = (a_scl * s[i][j] + c_add) * mask[(size_t)gr * 512 + gc];
                }
            }

            // online softmax (rows shared among the 16 threads with equal tr)
#pragma unroll
            for (int i = 0; i < 4; i++) {
                float tm = s[i][0];
#pragma unroll
                for (int j = 1; j < 4; j++) tm = fmaxf(tm, s[i][j]);
#pragma unroll
                for (int off = 1; off < 16; off <<= 1)
                    tm = fmaxf(tm, __shfl_xor_sync(0xffffffffu, tm, off));
                float nm  = fmaxf(m_[i], tm);
                float fac = __expf(m_[i] - nm);
                float rs  = 0.f;
#pragma unroll
                for (int j = 0; j < 4; j++) {
                    float p = __expf(s[i][j] - nm);
                    s[i][j] = p;
                    rs += p;
                }
#pragma unroll
                for (int off = 1; off < 16; off <<= 1)
                    rs += __shfl_xor_sync(0xffffffffu, rs, off);
                l_[i] = l_[i] * fac + rs;
                m_[i] = nm;
#pragma unroll
                for (int j = 0; j < 4; j++) oacc[i][j] *= fac;
                // stage P to smem
#pragma unroll
                for (int j = 0; j < 4; j++)
                    Ps[(tr + 16 * i) * 65 + tc + 16 * j] = s[i][j];
            }
            __syncthreads();

            // O += P * V
#pragma unroll 4
            for (int kk = 0; kk < 64; kk++) {
                float p4[4], v4[4];
#pragma unroll
                for (int i = 0; i < 4; i++) p4[i] = Ps[(tr + 16 * i) * 65 + kk];
#pragma unroll
                for (int i = 0; i < 4; i++) v4[i] = Vs[kk * 65 + tc + 16 * i];
#pragma unroll
                for (int i = 0; i < 4; i++)
#pragma unroll
                    for (int j = 0; j < 4; j++) oacc[i][j] += p4[i] * v4[j];
            }
        }

        // head epilogue: fin += w_head[h] * O / l
        float wh = w_head[h];
#pragma unroll
        for (int i = 0; i < 4; i++) {
            float inv = wh / l_[i];
#pragma unroll
            for (int j = 0; j < 4; j++) fin[i][j] += oacc[i][j] * inv;
        }
    }

    // write out (bt, l, e)
#pragma unroll
    for (int i = 0; i < 4; i++) {
        int l = row0 + tr + 16 * i;
#pragma unroll
        for (int j = 0; j < 4; j++) {
            int e = tc + 16 * j;
            out[((size_t)bt * 512 + l) * 64 + e] = fin[i][j];
        }
    }
}

extern "C" void kernel_launch(void* const* d_in, const int* in_sizes, int n_in,
                              void* d_out, int out_size) {
    const float* queries = (const float*)d_in[0];
    const float* keys    = (const float*)d_in[1];
    const float* values  = (const float*)d_in[2];
    const float* mask    = (const float*)d_in[3];
    const float* Wq      = (const float*)d_in[4];
    const float* Wk      = (const float*)d_in[5];
    const float* Wv      = (const float*)d_in[6];
    const float* w_head  = (const float*)d_in[7];
    const float* tau     = (const float*)d_in[8];
    const float* delta   = (const float*)d_in[9];
    float* out = (float*)d_out;

    float *qp, *kp, *vp;
    cudaGetSymbolAddress((void**)&qp, g_Q);
    cudaGetSymbolAddress((void**)&kp, g_K);
    cudaGetSymbolAddress((void**)&vp, g_V);

    dim3 pgrid(128, 4);      // M=16384/128, N=512/128
    proj_kernel<<<pgrid, 256>>>(queries, Wq, qp);
    proj_kernel<<<pgrid, 256>>>(keys,    Wk, kp);
    proj_kernel<<<pgrid, 256>>>(values,  Wv, vp);

    const int smem = 4 * 4160 * (int)sizeof(float);   // 66560 B
    cudaFuncSetAttribute(attn_kernel, cudaFuncAttributeMaxDynamicSharedMemorySize, smem);
    dim3 agrid(8, 32);       // (L/64, B*T)
    attn_kernel<<<agrid, 256, smem>>>(mask, w_head, tau, delta, out);
}

// round 2
// speedup vs baseline: 3.1460x; 3.1460x over previous
#include <cuda_runtime.h>
#include <math.h>
#include <stdint.h>

#define BT_ 32      // B*T
#define H_ 8
#define L_ 512
#define E_ 64
#define D_ 512

// Scratch for projected Q/K/V, layout (bt, h, l, e)
__device__ float g_Q[BT_ * H_ * L_ * E_];
__device__ float g_K[BT_ * H_ * L_ * E_];
__device__ float g_V[BT_ * H_ * L_ * E_];

__device__ __forceinline__ uint32_t f2tf(float f) {
    uint32_t u;
    asm("cvt.rna.tf32.f32 %0, %1;" : "=r"(u) : "f"(f));
    return u;
}

__device__ __forceinline__ void mma8(float* c, const uint32_t* a, const uint32_t* b) {
    asm volatile(
        "mma.sync.aligned.m16n8k8.row.col.f32.tf32.tf32.f32 "
        "{%0,%1,%2,%3}, {%4,%5,%6,%7}, {%8,%9}, {%0,%1,%2,%3};\n"
        : "+f"(c[0]), "+f"(c[1]), "+f"(c[2]), "+f"(c[3])
        : "r"(a[0]), "r"(a[1]), "r"(a[2]), "r"(a[3]), "r"(b[0]), "r"(b[1]));
}

// ---------------------------------------------------------------------------
// Projection GEMM (tf32 tensor cores): C(16384x512) = X(16384x512)*W(512x512)
// scattered to (bt,h,l,e). Block 128x128, BK=16, 256 thr / 8 warps,
// warp tile 32(M) x 64(N) = 2 x 8 mma tiles.
// ---------------------------------------------------------------------------
__global__ __launch_bounds__(256) void proj_tf32(const float* __restrict__ X,
                                                 const float* __restrict__ W,
                                                 float* __restrict__ out) {
    __shared__ float As[128 * 20];   // As[m][k], stride 20 (conflict-free frag loads)
    __shared__ float Bs[16 * 136];   // Bs[k][n], stride 136 (8 mod 32)

    const int tid = threadIdx.x;
    const int lane = tid & 31, wid = tid >> 5;
    const int g = lane >> 2, tig = lane & 3;
    const int warp_m = wid & 3, warp_n = wid >> 2;   // 4 x 2 warp grid
    const int bm = blockIdx.x * 128;
    const int bn = blockIdx.y * 128;

    float c[2][8][4];
#pragma unroll
    for (int mt = 0; mt < 2; mt++)
#pragma unroll
        for (int nt = 0; nt < 8; nt++)
#pragma unroll
            for (int i = 0; i < 4; i++) c[mt][nt][i] = 0.f;

    for (int k0 = 0; k0 < 512; k0 += 16) {
#pragma unroll
        for (int it = 0; it < 2; it++) {
            int f = it * 256 + tid;
            int row = f >> 2, c4 = (f & 3) * 4;
            *(float4*)&As[row * 20 + c4] =
                *(const float4*)(X + (size_t)(bm + row) * 512 + k0 + c4);
        }
#pragma unroll
        for (int it = 0; it < 2; it++) {
            int f = it * 256 + tid;
            int row = f >> 5, c4 = (f & 31) * 4;
            *(float4*)&Bs[row * 136 + c4] =
                *(const float4*)(W + (size_t)(k0 + row) * 512 + bn + c4);
        }
        __syncthreads();

#pragma unroll
        for (int ks = 0; ks < 16; ks += 8) {
            uint32_t a[2][4], b[8][2];
#pragma unroll
            for (int mt = 0; mt < 2; mt++) {
                int r = warp_m * 32 + mt * 16 + g;
                a[mt][0] = f2tf(As[r * 20 + ks + tig]);
                a[mt][1] = f2tf(As[(r + 8) * 20 + ks + tig]);
                a[mt][2] = f2tf(As[r * 20 + ks + tig + 4]);
                a[mt][3] = f2tf(As[(r + 8) * 20 + ks + tig + 4]);
            }
#pragma unroll
            for (int nt = 0; nt < 8; nt++) {
                int col = warp_n * 64 + nt * 8 + g;
                b[nt][0] = f2tf(Bs[(ks + tig) * 136 + col]);
                b[nt][1] = f2tf(Bs[(ks + tig + 4) * 136 + col]);
            }
#pragma unroll
            for (int mt = 0; mt < 2; mt++)
#pragma unroll
                for (int nt = 0; nt < 8; nt++)
                    mma8(c[mt][nt], a[mt], b[nt]);
        }
        __syncthreads();
    }

    // epilogue: scatter to (bt,h,l,e); n-tile 8-aligned => e,e+1 same head
#pragma unroll
    for (int mt = 0; mt < 2; mt++) {
#pragma unroll
        for (int nt = 0; nt < 8; nt++) {
            int n = bn + warp_n * 64 + nt * 8 + 2 * tig;
            int h = n >> 6, e = n & 63;
            int r1 = bm + warp_m * 32 + mt * 16 + g;
            int bt1 = r1 >> 9, l1 = r1 & 511;
            float2 v0 = make_float2(c[mt][nt][0], c[mt][nt][1]);
            *(float2*)&out[((size_t)(bt1 * 8 + h) * 512 + l1) * 64 + e] = v0;
            int r2 = r1 + 8;
            int bt2 = r2 >> 9, l2 = r2 & 511;
            float2 v1 = make_float2(c[mt][nt][2], c[mt][nt][3]);
            *(float2*)&out[((size_t)(bt2 * 8 + h) * 512 + l2) * 64 + e] = v1;
        }
    }
}

// ---------------------------------------------------------------------------
// Flash attention (tf32 tensor cores). Grid (L/64, BT), 128 thr / 4 warps.
// Each warp: 16 rows x 64 cols of S per jb-tile. Heads looped inside,
// weighted-summed into fin. Smem strides chosen for conflict-free frag loads.
// ---------------------------------------------------------------------------
__global__ __launch_bounds__(128) void attn_tf32(const float* __restrict__ mask,
                                                 const float* __restrict__ w_head,
                                                 const float* __restrict__ tau_p,
                                                 const float* __restrict__ delta_p,
                                                 float* __restrict__ out) {
    extern __shared__ float sm[];
    float* Qs = sm;                 // 64 x 68
    float* Ks = sm + 64 * 68;       // 64 x 68
    float* Ps = sm + 2 * 64 * 68;   // 64 x 68
    float* Vs = sm + 3 * 64 * 68;   // 64 x 72

    const int tid = threadIdx.x;
    const int lane = tid & 31, wid = tid >> 5;
    const int g = lane >> 2, tig = lane & 3;
    const int bt = blockIdx.y;
    const int row0 = blockIdx.x * 64;
    const int wrow = wid * 16;

    const float a_scl = tau_p[0] * 0.125f;
    const float c_add = delta_p[0] * 0.125f;

    float fin[8][4];
#pragma unroll
    for (int nt = 0; nt < 8; nt++)
#pragma unroll
        for (int i = 0; i < 4; i++) fin[nt][i] = 0.f;

    for (int h = 0; h < 8; h++) {
        const float* Qg = g_Q + (((size_t)(bt * 8 + h) * 512) + row0) * 64;
        const float* Kg = g_K + ((size_t)(bt * 8 + h) * 512) * 64;
        const float* Vg = g_V + ((size_t)(bt * 8 + h) * 512) * 64;

        __syncthreads();   // prior head's smem readers done
#pragma unroll
        for (int it = 0; it < 8; it++) {
            int f = it * 128 + tid;
            int row = f >> 4, cc = (f & 15) * 4;
            *(float4*)&Qs[row * 68 + cc] = *(const float4*)(Qg + row * 64 + cc);
        }
        __syncthreads();

        // Preload Q fragments for this head (reused across all jb)
        uint32_t qa[8][4];
#pragma unroll
        for (int ks = 0; ks < 8; ks++) {
            qa[ks][0] = f2tf(Qs[(wrow + g) * 68 + ks * 8 + tig]);
            qa[ks][1] = f2tf(Qs[(wrow + g + 8) * 68 + ks * 8 + tig]);
            qa[ks][2] = f2tf(Qs[(wrow + g) * 68 + ks * 8 + tig + 4]);
            qa[ks][3] = f2tf(Qs[(wrow + g + 8) * 68 + ks * 8 + tig + 4]);
        }

        float m1 = -INFINITY, m2 = -INFINITY, l1 = 0.f, l2 = 0.f;
        float oacc[8][4];
#pragma unroll
        for (int nt = 0; nt < 8; nt++)
#pragma unroll
            for (int i = 0; i < 4; i++) oacc[nt][i] = 0.f;

        for (int jb = 0; jb < 8; jb++) {
            __syncthreads();   // previous PV done before overwriting Ks/Vs
#pragma unroll
            for (int it = 0; it < 8; it++) {
                int f = it * 128 + tid;
                int row = f >> 4, cc = (f & 15) * 4;
                *(float4*)&Ks[row * 68 + cc] =
                    *(const float4*)(Kg + (jb * 64 + row) * 64 + cc);
                *(float4*)&Vs[row * 72 + cc] =
                    *(const float4*)(Vg + (jb * 64 + row) * 64 + cc);
            }
            __syncthreads();

            // S = Q K^T
            float sacc[8][4];
#pragma unroll
            for (int nt = 0; nt < 8; nt++)
#pragma unroll
                for (int i = 0; i < 4; i++) sacc[nt][i] = 0.f;
#pragma unroll
            for (int ks = 0; ks < 8; ks++) {
                uint32_t kb[8][2];
#pragma unroll
                for (int nt = 0; nt < 8; nt++) {
                    kb[nt][0] = f2tf(Ks[(nt * 8 + g) * 68 + ks * 8 + tig]);
                    kb[nt][1] = f2tf(Ks[(nt * 8 + g) * 68 + ks * 8 + tig + 4]);
                }
#pragma unroll
                for (int nt = 0; nt < 8; nt++)
                    mma8(sacc[nt], qa[ks], kb[nt]);
            }

            // rescale + scale + multiplicative mask
            const int gr1 = row0 + wrow + g;
            const int gr2 = gr1 + 8;
#pragma unroll
            for (int nt = 0; nt < 8; nt++) {
                int gc = jb * 64 + nt * 8 + 2 * tig;
                float2 mk1 = *(const float2*)(mask + (size_t)gr1 * 512 + gc);
                float2 mk2 = *(const float2*)(mask + (size_t)gr2 * 512 + gc);
                sacc[nt][0] = fmaf(a_scl, sacc[nt][0], c_add) * mk1.x;
                sacc[nt][1] = fmaf(a_scl, sacc[nt][1], c_add) * mk1.y;
                sacc[nt][2] = fmaf(a_scl, sacc[nt][2], c_add) * mk2.x;
                sacc[nt][3] = fmaf(a_scl, sacc[nt][3], c_add) * mk2.y;
            }

            // online softmax; rows owned by quads (reduce via xor 1,2)
            float rm1 = -INFINITY, rm2 = -INFINITY;
#pragma unroll
            for (int nt = 0; nt < 8; nt++) {
                rm1 = fmaxf(rm1, fmaxf(sacc[nt][0], sacc[nt][1]));
                rm2 = fmaxf(rm2, fmaxf(sacc[nt][2], sacc[nt][3]));
            }
#pragma unroll
            for (int off = 1; off < 4; off <<= 1) {
                rm1 = fmaxf(rm1, __shfl_xor_sync(0xffffffffu, rm1, off));
                rm2 = fmaxf(rm2, __shfl_xor_sync(0xffffffffu, rm2, off));
            }
            float nm1 = fmaxf(m1, rm1), nm2 = fmaxf(m2, rm2);
            float fac1 = __expf(m1 - nm1), fac2 = __expf(m2 - nm2);
            float rs1 = 0.f, rs2 = 0.f;
#pragma unroll
            for (int nt = 0; nt < 8; nt++) {
                sacc[nt][0] = __expf(sacc[nt][0] - nm1);
                sacc[nt][1] = __expf(sacc[nt][1] - nm1);
                sacc[nt][2] = __expf(sacc[nt][2] - nm2);
                sacc[nt][3] = __expf(sacc[nt][3] - nm2);
                rs1 += sacc[nt][0] + sacc[nt][1];
                rs2 += sacc[nt][2] + sacc[nt][3];
            }
#pragma unroll
            for (int off = 1; off < 4; off <<= 1) {
                rs1 += __shfl_xor_sync(0xffffffffu, rs1, off);
                rs2 += __shfl_xor_sync(0xffffffffu, rs2, off);
            }
            l1 = l1 * fac1 + rs1;  m1 = nm1;
            l2 = l2 * fac2 + rs2;  m2 = nm2;
#pragma unroll
            for (int nt = 0; nt < 8; nt++) {
                oacc[nt][0] *= fac1;  oacc[nt][1] *= fac1;
                oacc[nt][2] *= fac2;  oacc[nt][3] *= fac2;
            }
            // stage P (C-layout -> smem -> A-frag layout)
#pragma unroll
            for (int nt = 0; nt < 8; nt++) {
                int cc = nt * 8 + 2 * tig;
                *(float2*)&Ps[(wrow + g) * 68 + cc] =
                    make_float2(sacc[nt][0], sacc[nt][1]);
                *(float2*)&Ps[(wrow + g + 8) * 68 + cc] =
                    make_float2(sacc[nt][2], sacc[nt][3]);
            }
            __syncthreads();

            // O += P V
#pragma unroll
            for (int ks = 0; ks < 8; ks++) {
                uint32_t pa[4], vb[8][2];
                pa[0] = f2tf(Ps[(wrow + g) * 68 + ks * 8 + tig]);
                pa[1] = f2tf(Ps[(wrow + g + 8) * 68 + ks * 8 + tig]);
                pa[2] = f2tf(Ps[(wrow + g) * 68 + ks * 8 + tig + 4]);
                pa[3] = f2tf(Ps[(wrow + g + 8) * 68 + ks * 8 + tig + 4]);
#pragma unroll
                for (int nt = 0; nt < 8; nt++) {
                    vb[nt][0] = f2tf(Vs[(ks * 8 + tig) * 72 + nt * 8 + g]);
                    vb[nt][1] = f2tf(Vs[(ks * 8 + tig + 4) * 72 + nt * 8 + g]);
                }
#pragma unroll
                for (int nt = 0; nt < 8; nt++)
                    mma8(oacc[nt], pa, vb[nt]);
            }
        }

        const float wh = w_head[h];
        const float i1 = wh / l1, i2 = wh / l2;
#pragma unroll
        for (int nt = 0; nt < 8; nt++) {
            fin[nt][0] += oacc[nt][0] * i1;
            fin[nt][1] += oacc[nt][1] * i1;
            fin[nt][2] += oacc[nt][2] * i2;
            fin[nt][3] += oacc[nt][3] * i2;
        }
    }

    const int l1r = row0 + wrow + g, l2r = l1r + 8;
#pragma unroll
    for (int nt = 0; nt < 8; nt++) {
        int e = nt * 8 + 2 * tig;
        *(float2*)&out[((size_t)bt * 512 + l1r) * 64 + e] =
            make_float2(fin[nt][0], fin[nt][1]);
        *(float2*)&out[((size_t)bt * 512 + l2r) * 64 + e] =
            make_float2(fin[nt][2], fin[nt][3]);
    }
}

extern "C" void kernel_launch(void* const* d_in, const int* in_sizes, int n_in,
                              void* d_out, int out_size) {
    const float* queries = (const float*)d_in[0];
    const float* keys    = (const float*)d_in[1];
    const float* values  = (const float*)d_in[2];
    const float* mask    = (const float*)d_in[3];
    const float* Wq      = (const float*)d_in[4];
    const float* Wk      = (const float*)d_in[5];
    const float* Wv      = (const float*)d_in[6];
    const float* w_head  = (const float*)d_in[7];
    const float* tau     = (const float*)d_in[8];
    const float* delta   = (const float*)d_in[9];
    float* out = (float*)d_out;

    float *qp, *kp, *vp;
    cudaGetSymbolAddress((void**)&qp, g_Q);
    cudaGetSymbolAddress((void**)&kp, g_K);
    cudaGetSymbolAddress((void**)&vp, g_V);

    dim3 pgrid(128, 4);
    proj_tf32<<<pgrid, 256>>>(queries, Wq, qp);
    proj_tf32<<<pgrid, 256>>>(keys,    Wk, kp);
    proj_tf32<<<pgrid, 256>>>(values,  Wv, vp);

    const int smem = (3 * 64 * 68 + 64 * 72) * (int)sizeof(float);  // 70656 B
    static int cfg_done = 0;
    cudaFuncSetAttribute(attn_tf32, cudaFuncAttributeMaxDynamicSharedMemorySize, smem);
    (void)cfg_done;
    dim3 agrid(8, 32);
    attn_tf32<<<agrid, 128, smem>>>(mask, w_head, tau, delta, out);
}

// round 3
// speedup vs baseline: 3.7929x; 1.2056x over previous
#include <cuda_runtime.h>
#include <math.h>
#include <stdint.h>

#define BT_ 32
#define H_ 8
#define L_ 512
#define E_ 64
#define D_ 512
#define OUTN (BT_ * L_ * E_)     // 1M floats

__device__ float g_Q[BT_ * H_ * L_ * E_];
__device__ float g_K[BT_ * H_ * L_ * E_];
__device__ float g_V[BT_ * H_ * L_ * E_];
__device__ float g_part[H_ * OUTN];   // per-head weighted partials

__device__ __forceinline__ uint32_t f2tf(float f) {
    uint32_t u;
    asm("cvt.rna.tf32.f32 %0, %1;" : "=r"(u) : "f"(f));
    return u;
}

__device__ __forceinline__ void mma8(float* c, const uint32_t* a, const uint32_t* b) {
    asm volatile(
        "mma.sync.aligned.m16n8k8.row.col.f32.tf32.tf32.f32 "
        "{%0,%1,%2,%3}, {%4,%5,%6,%7}, {%8,%9}, {%0,%1,%2,%3};\n"
        : "+f"(c[0]), "+f"(c[1]), "+f"(c[2]), "+f"(c[3])
        : "r"(a[0]), "r"(a[1]), "r"(a[2]), "r"(a[3]), "r"(b[0]), "r"(b[1]));
}

// ---------------------------------------------------------------------------
// Fused projection GEMMs (tf32): blockIdx.z in {0,1,2} selects (X, W, out).
// C(16384x512) = X * W, scattered to (bt,h,l,e). Block 128x128, BK=16,
// 256 thr / 8 warps, warp tile 32x64. Smem holds pre-converted tf32 bits.
// ---------------------------------------------------------------------------
__global__ __launch_bounds__(256) void proj3(const float* __restrict__ Xq,
                                             const float* __restrict__ Xk,
                                             const float* __restrict__ Xv,
                                             const float* __restrict__ Wq,
                                             const float* __restrict__ Wk,
                                             const float* __restrict__ Wv) {
    __shared__ uint32_t As[128 * 20];   // As[m][k] tf32 bits
    __shared__ uint32_t Bs[16 * 136];   // Bs[k][n] tf32 bits

    const float* X;
    const float* W;
    float* out;
    if (blockIdx.z == 0)      { X = Xq; W = Wq; out = g_Q; }
    else if (blockIdx.z == 1) { X = Xk; W = Wk; out = g_K; }
    else                      { X = Xv; W = Wv; out = g_V; }

    const int tid = threadIdx.x;
    const int lane = tid & 31, wid = tid >> 5;
    const int g = lane >> 2, tig = lane & 3;
    const int warp_m = wid & 3, warp_n = wid >> 2;
    const int bm = blockIdx.x * 128;
    const int bn = blockIdx.y * 128;

    float c[2][8][4];
#pragma unroll
    for (int mt = 0; mt < 2; mt++)
#pragma unroll
        for (int nt = 0; nt < 8; nt++)
#pragma unroll
            for (int i = 0; i < 4; i++) c[mt][nt][i] = 0.f;

    for (int k0 = 0; k0 < 512; k0 += 16) {
#pragma unroll
        for (int it = 0; it < 2; it++) {
            int f = it * 256 + tid;
            int row = f >> 2, c4 = (f & 3) * 4;
            float4 v = *(const float4*)(X + (size_t)(bm + row) * 512 + k0 + c4);
            uint4 u = make_uint4(f2tf(v.x), f2tf(v.y), f2tf(v.z), f2tf(v.w));
            *(uint4*)&As[row * 20 + c4] = u;
        }
#pragma unroll
        for (int it = 0; it < 2; it++) {
            int f = it * 256 + tid;
            int row = f >> 5, c4 = (f & 31) * 4;
            float4 v = *(const float4*)(W + (size_t)(k0 + row) * 512 + bn + c4);
            uint4 u = make_uint4(f2tf(v.x), f2tf(v.y), f2tf(v.z), f2tf(v.w));
            *(uint4*)&Bs[row * 136 + c4] = u;
        }
        __syncthreads();

#pragma unroll
        for (int ks = 0; ks < 16; ks += 8) {
            uint32_t a[2][4], b[8][2];
#pragma unroll
            for (int mt = 0; mt < 2; mt++) {
                int r = warp_m * 32 + mt * 16 + g;
                a[mt][0] = As[r * 20 + ks + tig];
                a[mt][1] = As[(r + 8) * 20 + ks + tig];
                a[mt][2] = As[r * 20 + ks + tig + 4];
                a[mt][3] = As[(r + 8) * 20 + ks + tig + 4];
            }
#pragma unroll
            for (int nt = 0; nt < 8; nt++) {
                int col = warp_n * 64 + nt * 8 + g;
                b[nt][0] = Bs[(ks + tig) * 136 + col];
                b[nt][1] = Bs[(ks + tig + 4) * 136 + col];
            }
#pragma unroll
            for (int mt = 0; mt < 2; mt++)
#pragma unroll
                for (int nt = 0; nt < 8; nt++)
                    mma8(c[mt][nt], a[mt], b[nt]);
        }
        __syncthreads();
    }

#pragma unroll
    for (int mt = 0; mt < 2; mt++) {
#pragma unroll
        for (int nt = 0; nt < 8; nt++) {
            int n = bn + warp_n * 64 + nt * 8 + 2 * tig;
            int h = n >> 6, e = n & 63;
            int r1 = bm + warp_m * 32 + mt * 16 + g;
            int bt1 = r1 >> 9, l1 = r1 & 511;
            *(float2*)&out[((size_t)(bt1 * 8 + h) * 512 + l1) * 64 + e] =
                make_float2(c[mt][nt][0], c[mt][nt][1]);
            int r2 = r1 + 8;
            int bt2 = r2 >> 9, l2 = r2 & 511;
            *(float2*)&out[((size_t)(bt2 * 8 + h) * 512 + l2) * 64 + e] =
                make_float2(c[mt][nt][2], c[mt][nt][3]);
        }
    }
}

// ---------------------------------------------------------------------------
// Flash attention per head. Grid (L/64, BT, H), 128 thr / 4 warps.
// Writes w_head[h] * softmax(...) @ V partial to g_part[h]. Smem holds
// pre-converted tf32 bits; Qs is reused as Ps after Q-fragment preload.
// ---------------------------------------------------------------------------
__global__ __launch_bounds__(128, 3) void attn3(const float* __restrict__ mask,
                                                const float* __restrict__ w_head,
                                                const float* __restrict__ tau_p,
                                                const float* __restrict__ delta_p) {
    extern __shared__ uint32_t smu[];
    uint32_t* Qs = smu;                 // 64 x 68 (reused as Ps)
    uint32_t* Ks = smu + 64 * 68;       // 64 x 68
    uint32_t* Vs = smu + 2 * 64 * 68;   // 64 x 72

    const int tid = threadIdx.x;
    const int lane = tid & 31, wid = tid >> 5;
    const int g = lane >> 2, tig = lane & 3;
    const int bt = blockIdx.y;
    const int h  = blockIdx.z;
    const int row0 = blockIdx.x * 64;
    const int wrow = wid * 16;

    const float a_scl = tau_p[0] * 0.125f;
    const float c_add = delta_p[0] * 0.125f;

    const float* Qg = g_Q + (((size_t)(bt * 8 + h) * 512) + row0) * 64;
    const float* Kg = g_K + ((size_t)(bt * 8 + h) * 512) * 64;
    const float* Vg = g_V + ((size_t)(bt * 8 + h) * 512) * 64;

    // Load + convert Q tile
#pragma unroll
    for (int it = 0; it < 8; it++) {
        int f = it * 128 + tid;
        int row = f >> 4, cc = (f & 15) * 4;
        float4 v = *(const float4*)(Qg + row * 64 + cc);
        *(uint4*)&Qs[row * 68 + cc] =
            make_uint4(f2tf(v.x), f2tf(v.y), f2tf(v.z), f2tf(v.w));
    }
    __syncthreads();

    // Preload Q fragments (then Qs becomes Ps)
    uint32_t qa[8][4];
#pragma unroll
    for (int ks = 0; ks < 8; ks++) {
        qa[ks][0] = Qs[(wrow + g) * 68 + ks * 8 + tig];
        qa[ks][1] = Qs[(wrow + g + 8) * 68 + ks * 8 + tig];
        qa[ks][2] = Qs[(wrow + g) * 68 + ks * 8 + tig + 4];
        qa[ks][3] = Qs[(wrow + g + 8) * 68 + ks * 8 + tig + 4];
    }

    float m1 = -INFINITY, m2 = -INFINITY, l1 = 0.f, l2 = 0.f;
    float oacc[8][4];
#pragma unroll
    for (int nt = 0; nt < 8; nt++)
#pragma unroll
        for (int i = 0; i < 4; i++) oacc[nt][i] = 0.f;

    for (int jb = 0; jb < 8; jb++) {
        __syncthreads();   // all warps done with Ks/Vs (and Q-frag preload)
#pragma unroll
        for (int it = 0; it < 8; it++) {
            int f = it * 128 + tid;
            int row = f >> 4, cc = (f & 15) * 4;
            float4 vk = *(const float4*)(Kg + (jb * 64 + row) * 64 + cc);
            *(uint4*)&Ks[row * 68 + cc] =
                make_uint4(f2tf(vk.x), f2tf(vk.y), f2tf(vk.z), f2tf(vk.w));
            float4 vv = *(const float4*)(Vg + (jb * 64 + row) * 64 + cc);
            *(uint4*)&Vs[row * 72 + cc] =
                make_uint4(f2tf(vv.x), f2tf(vv.y), f2tf(vv.z), f2tf(vv.w));
        }
        __syncthreads();

        // S = Q K^T
        float sacc[8][4];
#pragma unroll
        for (int nt = 0; nt < 8; nt++)
#pragma unroll
            for (int i = 0; i < 4; i++) sacc[nt][i] = 0.f;
#pragma unroll
        for (int ks = 0; ks < 8; ks++) {
            uint32_t kb[8][2];
#pragma unroll
            for (int nt = 0; nt < 8; nt++) {
                kb[nt][0] = Ks[(nt * 8 + g) * 68 + ks * 8 + tig];
                kb[nt][1] = Ks[(nt * 8 + g) * 68 + ks * 8 + tig + 4];
            }
#pragma unroll
            for (int nt = 0; nt < 8; nt++)
                mma8(sacc[nt], qa[ks], kb[nt]);
        }

        const int gr1 = row0 + wrow + g;
        const int gr2 = gr1 + 8;
#pragma unroll
        for (int nt = 0; nt < 8; nt++) {
            int gc = jb * 64 + nt * 8 + 2 * tig;
            float2 mk1 = *(const float2*)(mask + (size_t)gr1 * 512 + gc);
            float2 mk2 = *(const float2*)(mask + (size_t)gr2 * 512 + gc);
            sacc[nt][0] = fmaf(a_scl, sacc[nt][0], c_add) * mk1.x;
            sacc[nt][1] = fmaf(a_scl, sacc[nt][1], c_add) * mk1.y;
            sacc[nt][2] = fmaf(a_scl, sacc[nt][2], c_add) * mk2.x;
            sacc[nt][3] = fmaf(a_scl, sacc[nt][3], c_add) * mk2.y;
        }

        // online softmax (row quads; reduce via xor 1,2)
        float rm1 = -INFINITY, rm2 = -INFINITY;
#pragma unroll
        for (int nt = 0; nt < 8; nt++) {
            rm1 = fmaxf(rm1, fmaxf(sacc[nt][0], sacc[nt][1]));
            rm2 = fmaxf(rm2, fmaxf(sacc[nt][2], sacc[nt][3]));
        }
#pragma unroll
        for (int off = 1; off < 4; off <<= 1) {
            rm1 = fmaxf(rm1, __shfl_xor_sync(0xffffffffu, rm1, off));
            rm2 = fmaxf(rm2, __shfl_xor_sync(0xffffffffu, rm2, off));
        }
        float nm1 = fmaxf(m1, rm1), nm2 = fmaxf(m2, rm2);
        float fac1 = __expf(m1 - nm1), fac2 = __expf(m2 - nm2);
        float rs1 = 0.f, rs2 = 0.f;
#pragma unroll
        for (int nt = 0; nt < 8; nt++) {
            sacc[nt][0] = __expf(sacc[nt][0] - nm1);
            sacc[nt][1] = __expf(sacc[nt][1] - nm1);
            sacc[nt][2] = __expf(sacc[nt][2] - nm2);
            sacc[nt][3] = __expf(sacc[nt][3] - nm2);
            rs1 += sacc[nt][0] + sacc[nt][1];
            rs2 += sacc[nt][2] + sacc[nt][3];
        }
#pragma unroll
        for (int off = 1; off < 4; off <<= 1) {
            rs1 += __shfl_xor_sync(0xffffffffu, rs1, off);
            rs2 += __shfl_xor_sync(0xffffffffu, rs2, off);
        }
        l1 = l1 * fac1 + rs1;  m1 = nm1;
        l2 = l2 * fac2 + rs2;  m2 = nm2;
#pragma unroll
        for (int nt = 0; nt < 8; nt++) {
            oacc[nt][0] *= fac1;  oacc[nt][1] *= fac1;
            oacc[nt][2] *= fac2;  oacc[nt][3] *= fac2;
        }

        // stage P (converted) into Ps=Qs; rows are warp-private -> syncwarp only
#pragma unroll
        for (int nt = 0; nt < 8; nt++) {
            int cc = nt * 8 + 2 * tig;
            *(uint2*)&Qs[(wrow + g) * 68 + cc] =
                make_uint2(f2tf(sacc[nt][0]), f2tf(sacc[nt][1]));
            *(uint2*)&Qs[(wrow + g + 8) * 68 + cc] =
                make_uint2(f2tf(sacc[nt][2]), f2tf(sacc[nt][3]));
        }
        __syncwarp();

        // O += P V
#pragma unroll
        for (int ks = 0; ks < 8; ks++) {
            uint32_t pa[4], vb[8][2];
            pa[0] = Qs[(wrow + g) * 68 + ks * 8 + tig];
            pa[1] = Qs[(wrow + g + 8) * 68 + ks * 8 + tig];
            pa[2] = Qs[(wrow + g) * 68 + ks * 8 + tig + 4];
            pa[3] = Qs[(wrow + g + 8) * 68 + ks * 8 + tig + 4];
#pragma unroll
            for (int nt = 0; nt < 8; nt++) {
                vb[nt][0] = Vs[(ks * 8 + tig) * 72 + nt * 8 + g];
                vb[nt][1] = Vs[(ks * 8 + tig + 4) * 72 + nt * 8 + g];
            }
#pragma unroll
            for (int nt = 0; nt < 8; nt++)
                mma8(oacc[nt], pa, vb[nt]);
        }
    }

    const float wh = w_head[h];
    const float i1 = wh / l1, i2 = wh / l2;
    float* po = g_part + (size_t)h * OUTN;
    const int l1r = row0 + wrow + g, l2r = l1r + 8;
#pragma unroll
    for (int nt = 0; nt < 8; nt++) {
        int e = nt * 8 + 2 * tig;
        *(float2*)&po[((size_t)bt * 512 + l1r) * 64 + e] =
            make_float2(oacc[nt][0] * i1, oacc[nt][1] * i1);
        *(float2*)&po[((size_t)bt * 512 + l2r) * 64 + e] =
            make_float2(oacc[nt][2] * i2, oacc[nt][3] * i2);
    }
}

// Sum the 8 per-head partials into out (deterministic, vectorized).
__global__ __launch_bounds__(256) void reduce_out(float* __restrict__ out) {
    int i = blockIdx.x * 256 + threadIdx.x;     // float4 index, 262144 total
    const float4* p = (const float4*)g_part;
    float4 s = p[i];
#pragma unroll
    for (int h = 1; h < 8; h++) {
        float4 t = p[(size_t)h * (OUTN / 4) + i];
        s.x += t.x; s.y += t.y; s.z += t.z; s.w += t.w;
    }
    ((float4*)out)[i] = s;
}

extern "C" void kernel_launch(void* const* d_in, const int* in_sizes, int n_in,
                              void* d_out, int out_size) {
    const float* queries = (const float*)d_in[0];
    const float* keys    = (const float*)d_in[1];
    const float* values  = (const float*)d_in[2];
    const float* mask    = (const float*)d_in[3];
    const float* Wq      = (const float*)d_in[4];
    const float* Wk      = (const float*)d_in[5];
    const float* Wv      = (const float*)d_in[6];
    const float* w_head  = (const float*)d_in[7];
    const float* tau     = (const float*)d_in[8];
    const float* delta   = (const float*)d_in[9];
    float* out = (float*)d_out;

    dim3 pgrid(128, 4, 3);
    proj3<<<pgrid, 256>>>(queries, keys, values, Wq, Wk, Wv);

    const int smem = (2 * 64 * 68 + 64 * 72) * (int)sizeof(uint32_t);  // 53248 B
    cudaFuncSetAttribute(attn3, cudaFuncAttributeMaxDynamicSharedMemorySize, smem);
    dim3 agrid(8, 32, 8);
    attn3<<<agrid, 128, smem>>>(mask, w_head, tau, delta);

    reduce_out<<<OUTN / 4 / 256, 256>>>(out);
}